// round 1
// baseline (speedup 1.0000x reference)
#include <cuda_runtime.h>
#include <cuda_bf16.h>
#include <cstdint>
#include <cstdio>

// Problem constants
#define NN_   8192
#define T_    32
#define IN_   256
#define H_    256
#define H3_   768
#define E_    1024
#define NNZ_  65536
#define GCN_  256

// ---------------------------------------------------------------------------
// Scratch (static device globals; no runtime allocation)
// ---------------------------------------------------------------------------
__device__ float g_adj[(size_t)NN_ * NN_];      // 256 MB gram matrix
__device__ float g_xg[NN_ * H3_];               // per-step input gates
__device__ float g_hg[NN_ * H3_];               // per-step hidden gates
__device__ float g_h [NN_ * H_];                // GRU hidden state
__device__ float g_fa[NN_ * H_];                // feature ping (last / o2)
__device__ float g_fb[NN_ * H_];                // feature pong (o1 / o3)
__device__ float g_xw[NN_ * H_];                // HGC x@W
__device__ float g_agg[NN_ * H_];               // HGC node aggregation
__device__ float g_eb[E_ * H_];                 // HGC edge accumulator
__device__ float g_x2[NN_ * GCN_];              // o3 @ gcn_w
__device__ float g_y [NN_ * GCN_];              // dis_j * x2_j
__device__ float g_Dcnt[NN_];
__device__ float g_Dinv[NN_];
__device__ float g_Bcnt[E_];
__device__ float g_Binv[E_];
__device__ float g_dis[NN_];

// ---------------------------------------------------------------------------
// Generic tiled SGEMM: C[M,N] = A[M,K] * op(B) (+bias)
//   TRANSB=true : B is [N,K] row-major (use B^T)  -> NT
//   TRANSB=false: B is [K,N] row-major            -> NN
// All dims multiples of tile sizes (guaranteed by problem shapes).
// BM=BN=128, BK=16, 256 threads, 8x8 microtile.
// ---------------------------------------------------------------------------
template<bool TRANSB, bool BIAS>
__global__ __launch_bounds__(256)
void sgemm128(const float* __restrict__ A, int lda,
              const float* __restrict__ B, int ldb,
              float* __restrict__ C, int ldc,
              int K, const float* __restrict__ bias)
{
    __shared__ __align__(16) float As[16][132];
    __shared__ __align__(16) float Bs[16][132];

    const int bm = blockIdx.y * 128;
    const int bn = blockIdx.x * 128;
    const int tid = threadIdx.x;
    const int tx = tid & 15;         // 0..15 -> 8 cols each
    const int ty = tid >> 4;         // 0..15 -> 8 rows each

    float acc[8][8];
#pragma unroll
    for (int i = 0; i < 8; i++)
#pragma unroll
        for (int j = 0; j < 8; j++) acc[i][j] = 0.f;

    for (int k0 = 0; k0 < K; k0 += 16) {
        // A tile: 128 rows x 16 k (k-contiguous) -> As[k][m]
#pragma unroll
        for (int i = 0; i < 2; i++) {
            int id = tid + i * 256;
            int r  = id >> 2;
            int c4 = (id & 3) * 4;
            float4 v = *(const float4*)(A + (size_t)(bm + r) * lda + k0 + c4);
            As[c4 + 0][r] = v.x; As[c4 + 1][r] = v.y;
            As[c4 + 2][r] = v.z; As[c4 + 3][r] = v.w;
        }
        if (TRANSB) {
#pragma unroll
            for (int i = 0; i < 2; i++) {
                int id = tid + i * 256;
                int r  = id >> 2;
                int c4 = (id & 3) * 4;
                float4 v = *(const float4*)(B + (size_t)(bn + r) * ldb + k0 + c4);
                Bs[c4 + 0][r] = v.x; Bs[c4 + 1][r] = v.y;
                Bs[c4 + 2][r] = v.z; Bs[c4 + 3][r] = v.w;
            }
        } else {
#pragma unroll
            for (int i = 0; i < 2; i++) {
                int id = tid + i * 256;
                int kr = id >> 5;
                int c4 = (id & 31) * 4;
                float4 v = *(const float4*)(B + (size_t)(k0 + kr) * ldb + bn + c4);
                *(float4*)&Bs[kr][c4] = v;
            }
        }
        __syncthreads();

#pragma unroll
        for (int kk = 0; kk < 16; kk++) {
            float a[8], b[8];
            *(float4*)&a[0] = *(const float4*)&As[kk][ty * 8];
            *(float4*)&a[4] = *(const float4*)&As[kk][ty * 8 + 4];
            *(float4*)&b[0] = *(const float4*)&Bs[kk][tx * 8];
            *(float4*)&b[4] = *(const float4*)&Bs[kk][tx * 8 + 4];
#pragma unroll
            for (int i = 0; i < 8; i++)
#pragma unroll
                for (int j = 0; j < 8; j++)
                    acc[i][j] += a[i] * b[j];
        }
        __syncthreads();
    }

#pragma unroll
    for (int i = 0; i < 8; i++) {
        int row = bm + ty * 8 + i;
#pragma unroll
        for (int j = 0; j < 8; j += 4) {
            int col = bn + tx * 8 + j;
            float4 v = make_float4(acc[i][j], acc[i][j + 1], acc[i][j + 2], acc[i][j + 3]);
            if (BIAS) {
                v.x += bias[col];     v.y += bias[col + 1];
                v.z += bias[col + 2]; v.w += bias[col + 3];
            }
            *(float4*)(C + (size_t)row * ldc + col) = v;
        }
    }
}

// ---------------------------------------------------------------------------
// GRU support
// ---------------------------------------------------------------------------
__global__ void init_h_kernel(float* __restrict__ h, const float* __restrict__ h0)
{
    int idx = blockIdx.x * 256 + threadIdx.x;
    h[idx] = h0[idx & (H_ - 1)];
}

__global__ void gru_gate_kernel(const float* __restrict__ xg,
                                const float* __restrict__ hg,
                                float* __restrict__ h,
                                const int* __restrict__ slen,
                                float* __restrict__ last, int t)
{
    int idx = blockIdx.x * 256 + threadIdx.x;  // N*H
    int n = idx >> 8;
    int c = idx & 255;
    size_t base = (size_t)n * H3_ + c;
    float xr = xg[base], xz = xg[base + H_], xn = xg[base + 2 * H_];
    float hr = hg[base], hz = hg[base + H_], hn = hg[base + 2 * H_];
    float r = 1.f / (1.f + __expf(-(xr + hr)));
    float z = 1.f / (1.f + __expf(-(xz + hz)));
    float nn = tanhf(xn + r * hn);
    float hp = h[idx];
    float hnew = (1.f - z) * nn + z * hp;
    h[idx] = hnew;
    if (t == slen[n] - 1) last[idx] = hnew;
}

// ---------------------------------------------------------------------------
// Hypergraph conv support
// ---------------------------------------------------------------------------
__global__ void zero_kernel(float* __restrict__ p, int n4)
{
    int i = blockIdx.x * 256 + threadIdx.x;
    if (i < n4) ((float4*)p)[i] = make_float4(0.f, 0.f, 0.f, 0.f);
}

__global__ void count_deg_kernel(const int* __restrict__ node_idx,
                                 const int* __restrict__ edge_idx,
                                 float* __restrict__ D, float* __restrict__ B)
{
    int i = blockIdx.x * 256 + threadIdx.x;
    if (i < NNZ_) {
        atomicAdd(&D[node_idx[i]], 1.f);
        atomicAdd(&B[edge_idx[i]], 1.f);
    }
}

__global__ void make_inv_kernel(const float* __restrict__ cnt, float* __restrict__ inv, int n)
{
    int i = blockIdx.x * 256 + threadIdx.x;
    if (i < n) {
        float c = cnt[i];
        inv[i] = c > 0.f ? 1.f / c : 0.f;
    }
}

__global__ void scatter_edge_kernel(const float* __restrict__ xw,
                                    const int* __restrict__ node_idx,
                                    const int* __restrict__ edge_idx,
                                    float* __restrict__ eb)
{
    int idx = blockIdx.x * 256 + threadIdx.x;   // NNZ * 64
    int nz = idx >> 6;
    int c4 = (idx & 63) << 2;
    int n = node_idx[nz];
    int e = edge_idx[nz];
    float4 v = *(const float4*)(xw + (size_t)n * H_ + c4);
    float* dst = eb + (size_t)e * H_ + c4;
    atomicAdd(dst + 0, v.x); atomicAdd(dst + 1, v.y);
    atomicAdd(dst + 2, v.z); atomicAdd(dst + 3, v.w);
}

__global__ void scatter_node_kernel(const float* __restrict__ eb,
                                    const int* __restrict__ node_idx,
                                    const int* __restrict__ edge_idx,
                                    const float* __restrict__ Binv,
                                    float* __restrict__ agg)
{
    int idx = blockIdx.x * 256 + threadIdx.x;   // NNZ * 64
    int nz = idx >> 6;
    int c4 = (idx & 63) << 2;
    int n = node_idx[nz];
    int e = edge_idx[nz];
    float be = Binv[e];
    float4 v = *(const float4*)(eb + (size_t)e * H_ + c4);
    float* dst = agg + (size_t)n * H_ + c4;
    atomicAdd(dst + 0, v.x * be); atomicAdd(dst + 1, v.y * be);
    atomicAdd(dst + 2, v.z * be); atomicAdd(dst + 3, v.w * be);
}

__global__ void hgc_finish_kernel(const float* __restrict__ agg,
                                  const float* __restrict__ Dinv,
                                  const float* __restrict__ bias,
                                  const float* __restrict__ resid,
                                  float* __restrict__ out)
{
    int idx = blockIdx.x * 256 + threadIdx.x;   // N*H
    int n = idx >> 8;
    int c = idx & 255;
    out[idx] = agg[idx] * Dinv[n] + bias[c] + resid[idx];
}

// ---------------------------------------------------------------------------
// Final GCN: deg / dis, Y-scaling, masked GEMM
// ---------------------------------------------------------------------------
__global__ void deg_kernel(const float* __restrict__ adj,
                           const float* __restrict__ phi_p,
                           float* __restrict__ dis)
{
    int row = blockIdx.x;
    int tid = threadIdx.x;
    float thr = phi_p[0] * 65536.0f;
    const float* r = adj + (size_t)row * NN_;
    float c = 0.f;
    for (int j = tid * 4; j < NN_; j += 256 * 4) {
        float4 v = *(const float4*)(r + j);
        c += (v.x >= thr || j + 0 == row) ? 1.f : 0.f;
        c += (v.y >= thr || j + 1 == row) ? 1.f : 0.f;
        c += (v.z >= thr || j + 2 == row) ? 1.f : 0.f;
        c += (v.w >= thr || j + 3 == row) ? 1.f : 0.f;
    }
    __shared__ float sm[256];
    sm[tid] = c;
    __syncthreads();
    for (int s = 128; s > 0; s >>= 1) {
        if (tid < s) sm[tid] += sm[tid + s];
        __syncthreads();
    }
    if (tid == 0) {
        float d = sm[0];
        dis[row] = d > 0.f ? rsqrtf(d) : 0.f;
    }
}

__global__ void yscale_kernel(const float* __restrict__ x2,
                              const float* __restrict__ dis,
                              float* __restrict__ y)
{
    int idx = blockIdx.x * 256 + threadIdx.x;   // N*GCN
    int n = idx >> 8;
    y[idx] = x2[idx] * dis[n];
}

// out[i,d] = dis_i * sum_j mask(adj_ij) * Y[j,d] + bias[d]
// BM=64, BN=64, BK=32, 256 threads, 4x4 microtile. Grid (GCN/64, N/64).
__global__ __launch_bounds__(256)
void gcn_gemm_kernel(const float* __restrict__ adj,
                     const float* __restrict__ Y,
                     const float* __restrict__ dis,
                     const float* __restrict__ bias,
                     const float* __restrict__ phi_p,
                     float* __restrict__ out)
{
    __shared__ __align__(16) float As[32][68];
    __shared__ __align__(16) float Bs[32][68];

    const float thr = phi_p[0] * 65536.0f;
    const int bm = blockIdx.y * 64;
    const int bn = blockIdx.x * 64;
    const int tid = threadIdx.x;
    const int tx = tid & 15;
    const int ty = tid >> 4;

    float acc[4][4];
#pragma unroll
    for (int i = 0; i < 4; i++)
#pragma unroll
        for (int j = 0; j < 4; j++) acc[i][j] = 0.f;

    for (int k0 = 0; k0 < NN_; k0 += 32) {
        // adj tile: 64 rows x 32 cols, expand mask -> As[k][m]
#pragma unroll
        for (int i = 0; i < 2; i++) {
            int id = tid + i * 256;
            int r  = id >> 3;
            int c4 = (id & 7) * 4;
            int row = bm + r;
            int col = k0 + c4;
            float4 v = *(const float4*)(adj + (size_t)row * NN_ + col);
            As[c4 + 0][r] = (v.x >= thr || row == col + 0) ? 1.f : 0.f;
            As[c4 + 1][r] = (v.y >= thr || row == col + 1) ? 1.f : 0.f;
            As[c4 + 2][r] = (v.z >= thr || row == col + 2) ? 1.f : 0.f;
            As[c4 + 3][r] = (v.w >= thr || row == col + 3) ? 1.f : 0.f;
        }
        // Y tile: 32 k x 64 n
#pragma unroll
        for (int i = 0; i < 2; i++) {
            int id = tid + i * 256;
            int kr = id >> 4;
            int c4 = (id & 15) * 4;
            *(float4*)&Bs[kr][c4] = *(const float4*)(Y + (size_t)(k0 + kr) * GCN_ + bn + c4);
        }
        __syncthreads();

#pragma unroll
        for (int kk = 0; kk < 32; kk++) {
            float a[4], b[4];
            *(float4*)&a[0] = *(const float4*)&As[kk][ty * 4];
            *(float4*)&b[0] = *(const float4*)&Bs[kk][tx * 4];
#pragma unroll
            for (int i = 0; i < 4; i++)
#pragma unroll
                for (int j = 0; j < 4; j++)
                    acc[i][j] += a[i] * b[j];
        }
        __syncthreads();
    }

#pragma unroll
    for (int i = 0; i < 4; i++) {
        int row = bm + ty * 4 + i;
        float di = dis[row];
        int col = bn + tx * 4;
        float4 v = make_float4(di * acc[i][0] + bias[col],
                               di * acc[i][1] + bias[col + 1],
                               di * acc[i][2] + bias[col + 2],
                               di * acc[i][3] + bias[col + 3]);
        *(float4*)(out + (size_t)row * GCN_ + col) = v;
    }
}

// ---------------------------------------------------------------------------
// Host orchestration
// ---------------------------------------------------------------------------
static void hgc_layer(const float* in, const float* W, const float* b,
                      const int* node_idx, const int* edge_idx,
                      float* xw, float* eb, float* agg,
                      const float* Dinv, const float* Binv, float* outbuf)
{
    // xw = in @ W  (NN, 8192x256x256)
    sgemm128<false, false><<<dim3(H_ / 128, NN_ / 128), 256>>>(
        in, H_, W, H_, xw, H_, H_, nullptr);
    zero_kernel<<<(E_ * H_ / 4 + 255) / 256, 256>>>(eb, E_ * H_ / 4);
    scatter_edge_kernel<<<NNZ_ * 64 / 256, 256>>>(xw, node_idx, edge_idx, eb);
    zero_kernel<<<(NN_ * H_ / 4 + 255) / 256, 256>>>(agg, NN_ * H_ / 4);
    scatter_node_kernel<<<NNZ_ * 64 / 256, 256>>>(eb, node_idx, edge_idx, Binv, agg);
    hgc_finish_kernel<<<NN_ * H_ / 256, 256>>>(agg, Dinv, b, in, outbuf);
}

extern "C" void kernel_launch(void* const* d_in, const int* in_sizes, int n_in,
                              void* d_out, int out_size)
{
    (void)in_sizes; (void)n_in; (void)out_size;

    const float* x        = (const float*)d_in[0];
    const int*   hei      = (const int*)d_in[1];
    const int*   node_idx = hei;
    const int*   edge_idx = hei + NNZ_;
    const int*   slen     = (const int*)d_in[2];
    const float* h0       = (const float*)d_in[3];
    const float* W_ih     = (const float*)d_in[4];
    const float* W_hh     = (const float*)d_in[5];
    const float* b_ih     = (const float*)d_in[6];
    const float* b_hh     = (const float*)d_in[7];
    const float* w1 = (const float*)d_in[8];  const float* bb1 = (const float*)d_in[9];
    const float* w2 = (const float*)d_in[10]; const float* bb2 = (const float*)d_in[11];
    const float* w3 = (const float*)d_in[12]; const float* bb3 = (const float*)d_in[13];
    const float* phi = (const float*)d_in[14];
    const float* gw  = (const float*)d_in[15];
    const float* gb  = (const float*)d_in[16];
    float* out = (float*)d_out;

    float *adj, *xg, *hg, *h, *fa, *fb, *xw, *eb, *agg, *x2, *y;
    float *Dcnt, *Dinv, *Bcnt, *Binv, *dis;
    cudaGetSymbolAddress((void**)&adj,  g_adj);
    cudaGetSymbolAddress((void**)&xg,   g_xg);
    cudaGetSymbolAddress((void**)&hg,   g_hg);
    cudaGetSymbolAddress((void**)&h,    g_h);
    cudaGetSymbolAddress((void**)&fa,   g_fa);
    cudaGetSymbolAddress((void**)&fb,   g_fb);
    cudaGetSymbolAddress((void**)&xw,   g_xw);
    cudaGetSymbolAddress((void**)&eb,   g_eb);
    cudaGetSymbolAddress((void**)&agg,  g_agg);
    cudaGetSymbolAddress((void**)&x2,   g_x2);
    cudaGetSymbolAddress((void**)&y,    g_y);
    cudaGetSymbolAddress((void**)&Dcnt, g_Dcnt);
    cudaGetSymbolAddress((void**)&Dinv, g_Dinv);
    cudaGetSymbolAddress((void**)&Bcnt, g_Bcnt);
    cudaGetSymbolAddress((void**)&Binv, g_Binv);
    cudaGetSymbolAddress((void**)&dis,  g_dis);

    // ---------------- GRU ----------------
    init_h_kernel<<<NN_ * H_ / 256, 256>>>(h, h0);
    for (int t = 0; t < T_; t++) {
        // xg_t = x[:,t,:] @ W_ih^T + b_ih   (A rows stride T*IN, offset t*IN)
        sgemm128<true, true><<<dim3(H3_ / 128, NN_ / 128), 256>>>(
            x + (size_t)t * IN_, T_ * IN_, W_ih, IN_, xg, H3_, IN_, b_ih);
        // hg = h @ W_hh^T + b_hh
        sgemm128<true, true><<<dim3(H3_ / 128, NN_ / 128), 256>>>(
            h, H_, W_hh, H_, hg, H3_, H_, b_hh);
        gru_gate_kernel<<<NN_ * H_ / 256, 256>>>(xg, hg, h, slen, fa, t);
    }
    // fa now holds `last` [N,H]

    // ---------------- degrees (shared by 3 HGC layers) ----------------
    zero_kernel<<<(NN_ / 4 + 255) / 256, 256>>>(Dcnt, NN_ / 4);
    zero_kernel<<<(E_ / 4 + 255) / 256, 256>>>(Bcnt, E_ / 4);
    count_deg_kernel<<<NNZ_ / 256, 256>>>(node_idx, edge_idx, Dcnt, Bcnt);
    make_inv_kernel<<<(NN_ + 255) / 256, 256>>>(Dcnt, Dinv, NN_);
    make_inv_kernel<<<(E_ + 255) / 256, 256>>>(Bcnt, Binv, E_);

    // ---------------- 3 hypergraph conv layers with residuals ----------------
    hgc_layer(fa, w1, bb1, node_idx, edge_idx, xw, eb, agg, Dinv, Binv, fb); // o1 = fb
    hgc_layer(fb, w2, bb2, node_idx, edge_idx, xw, eb, agg, Dinv, Binv, fa); // o2 = fa
    hgc_layer(fa, w3, bb3, node_idx, edge_idx, xw, eb, agg, Dinv, Binv, fb); // o3 = fb

    // ---------------- final dense GCN ----------------
    // x2 = o3 @ gcn_w (NN)
    sgemm128<false, false><<<dim3(GCN_ / 128, NN_ / 128), 256>>>(
        fb, H_, gw, GCN_, x2, GCN_, H_, nullptr);
    // adj = o3 @ o3^T (NT), raw gram (compare vs phi*65536 later)
    sgemm128<true, false><<<dim3(NN_ / 128, NN_ / 128), 256>>>(
        fb, H_, fb, H_, adj, NN_, H_, nullptr);
    // dis_i = rsqrt(deg_i), deg includes forced diagonal
    deg_kernel<<<NN_, 256>>>(adj, phi, dis);
    // Y = dis_j * x2_j
    yscale_kernel<<<NN_ * GCN_ / 256, 256>>>(x2, dis, y);
    // out = dis_i * (mask(adj) @ Y) + gcn_b
    gcn_gemm_kernel<<<dim3(GCN_ / 64, NN_ / 64), 256>>>(adj, y, dis, gb, phi, out);
}

// round 2
// speedup vs baseline: 1.1420x; 1.1420x over previous
#include <cuda_runtime.h>
#include <cuda_bf16.h>
#include <cstdint>
#include <cstdio>

// Problem constants
#define NN_   8192
#define T_    32
#define IN_   256
#define H_    256
#define H3_   768
#define E_    1024
#define NNZ_  65536
#define GCN_  256

// ---------------------------------------------------------------------------
// Scratch (static device globals; no runtime allocation)
// ---------------------------------------------------------------------------
__device__ float g_adj[(size_t)NN_ * NN_];          // 256 MB gram matrix
__device__ float g_xgall[(size_t)NN_ * T_ * H3_];   // 805 MB precomputed input gates
__device__ float g_hg[NN_ * H3_];                   // per-step hidden gates
__device__ float g_h [NN_ * H_];                    // GRU hidden state
__device__ float g_fa[NN_ * H_];                    // feature ping (last / o2)
__device__ float g_fb[NN_ * H_];                    // feature pong (o1 / o3)
__device__ float g_xw[NN_ * H_];                    // HGC x@W
__device__ float g_agg[NN_ * H_];                   // HGC node aggregation
__device__ float g_eb[E_ * H_];                     // HGC edge accumulator
__device__ float g_x2[NN_ * GCN_];                  // o3 @ gcn_w
__device__ float g_y [NN_ * GCN_];                  // dis_j * x2_j
__device__ float g_Dcnt[NN_];
__device__ float g_Dinv[NN_];
__device__ float g_Bcnt[E_];
__device__ float g_Binv[E_];
__device__ float g_dis[NN_];

// ---------------------------------------------------------------------------
// Packed fp32x2 helpers (Blackwell sm_103a)
// ---------------------------------------------------------------------------
__device__ __forceinline__ void fma2(unsigned long long& d,
                                     unsigned long long a,
                                     unsigned long long b)
{
    asm("fma.rn.f32x2 %0, %1, %2, %0;" : "+l"(d) : "l"(a), "l"(b));
}

__device__ __forceinline__ unsigned long long dup2(float x)
{
    unsigned long long r;
    unsigned u = __float_as_uint(x);
    asm("mov.b64 %0, {%1, %1};" : "=l"(r) : "r"(u));
    return r;
}

__device__ __forceinline__ void unpack2(unsigned long long v, float& lo, float& hi)
{
    unsigned a, b;
    asm("mov.b64 {%0, %1}, %2;" : "=r"(a), "=r"(b) : "l"(v));
    lo = __uint_as_float(a);
    hi = __uint_as_float(b);
}

// ---------------------------------------------------------------------------
// Tiled SGEMM with packed f32x2 FMA + double-buffered smem.
// C[M,N] = A[M,K] * op(B) (+bias)
//   TRANSB=true : B is [N,K] row-major (use B^T)  -> NT
//   TRANSB=false: B is [K,N] row-major            -> NN
// BM=BN=128, BK=16, 256 threads, 8x8 microtile (stored as 8x4 f32x2 pairs).
// All dims multiples of tile sizes.
// ---------------------------------------------------------------------------
template<bool TRANSB, bool BIAS>
__global__ __launch_bounds__(256)
void sgemm_f2(const float* __restrict__ A, int lda,
              const float* __restrict__ B, int ldb,
              float* __restrict__ C, int ldc,
              int K, const float* __restrict__ bias)
{
    __shared__ __align__(16) float As[2][16][132];
    __shared__ __align__(16) float Bs[2][16][132];

    const int bm = blockIdx.y * 128;
    const int bn = blockIdx.x * 128;
    const int tid = threadIdx.x;
    const int tx = tid & 15;
    const int ty = tid >> 4;
    const int ar  = tid >> 2;          // 0..63
    const int ac4 = (tid & 3) * 4;     // 0,4,8,12
    const int bkr = tid >> 5;          // 0..7   (NN loader)
    const int bc4 = (tid & 31) * 4;    // 0..124 (NN loader)

    unsigned long long acc[8][4];
#pragma unroll
    for (int i = 0; i < 8; i++)
#pragma unroll
        for (int j = 0; j < 4; j++) acc[i][j] = 0ull;

    float4 a0v, a1v, b0v, b1v;

#define LOAD_TILE(k0)                                                         \
    do {                                                                      \
        const float* Ap = A + (size_t)(bm + ar) * lda + (k0) + ac4;          \
        a0v = *(const float4*)Ap;                                             \
        a1v = *(const float4*)(Ap + (size_t)64 * lda);                        \
        if (TRANSB) {                                                         \
            const float* Bp = B + (size_t)(bn + ar) * ldb + (k0) + ac4;      \
            b0v = *(const float4*)Bp;                                         \
            b1v = *(const float4*)(Bp + (size_t)64 * ldb);                    \
        } else {                                                              \
            const float* Bp = B + (size_t)((k0) + bkr) * ldb + bn + bc4;      \
            b0v = *(const float4*)Bp;                                         \
            b1v = *(const float4*)(Bp + (size_t)8 * ldb);                     \
        }                                                                     \
    } while (0)

#define STORE_TILE(buf)                                                       \
    do {                                                                      \
        As[buf][ac4 + 0][ar] = a0v.x; As[buf][ac4 + 1][ar] = a0v.y;           \
        As[buf][ac4 + 2][ar] = a0v.z; As[buf][ac4 + 3][ar] = a0v.w;           \
        As[buf][ac4 + 0][ar + 64] = a1v.x; As[buf][ac4 + 1][ar + 64] = a1v.y; \
        As[buf][ac4 + 2][ar + 64] = a1v.z; As[buf][ac4 + 3][ar + 64] = a1v.w; \
        if (TRANSB) {                                                         \
            Bs[buf][ac4 + 0][ar] = b0v.x; Bs[buf][ac4 + 1][ar] = b0v.y;       \
            Bs[buf][ac4 + 2][ar] = b0v.z; Bs[buf][ac4 + 3][ar] = b0v.w;       \
            Bs[buf][ac4 + 0][ar + 64] = b1v.x; Bs[buf][ac4 + 1][ar + 64] = b1v.y; \
            Bs[buf][ac4 + 2][ar + 64] = b1v.z; Bs[buf][ac4 + 3][ar + 64] = b1v.w; \
        } else {                                                              \
            *(float4*)&Bs[buf][bkr][bc4] = b0v;                               \
            *(float4*)&Bs[buf][bkr + 8][bc4] = b1v;                           \
        }                                                                     \
    } while (0)

    LOAD_TILE(0);
    STORE_TILE(0);
    __syncthreads();

    const int nk = K >> 4;
    for (int kt = 0; kt < nk; kt++) {
        const int cur = kt & 1;
        if (kt + 1 < nk) LOAD_TILE((kt + 1) * 16);

#pragma unroll
        for (int kk = 0; kk < 16; kk++) {
            float av[8];
            *(float4*)&av[0] = *(const float4*)&As[cur][kk][ty * 8];
            *(float4*)&av[4] = *(const float4*)&As[cur][kk][ty * 8 + 4];
            ulonglong2 bp0 = *(const ulonglong2*)&Bs[cur][kk][tx * 8];
            ulonglong2 bp1 = *(const ulonglong2*)&Bs[cur][kk][tx * 8 + 4];
#pragma unroll
            for (int i = 0; i < 8; i++) {
                unsigned long long ad = dup2(av[i]);
                fma2(acc[i][0], ad, bp0.x);
                fma2(acc[i][1], ad, bp0.y);
                fma2(acc[i][2], ad, bp1.x);
                fma2(acc[i][3], ad, bp1.y);
            }
        }
        if (kt + 1 < nk) STORE_TILE((kt + 1) & 1);
        __syncthreads();
    }
#undef LOAD_TILE
#undef STORE_TILE

    float bv[8];
    if (BIAS) {
        *(float4*)&bv[0] = *(const float4*)(bias + bn + tx * 8);
        *(float4*)&bv[4] = *(const float4*)(bias + bn + tx * 8 + 4);
    }

#pragma unroll
    for (int i = 0; i < 8; i++) {
        int row = bm + ty * 8 + i;
        float o[8];
#pragma unroll
        for (int j = 0; j < 4; j++) unpack2(acc[i][j], o[2 * j], o[2 * j + 1]);
        if (BIAS) {
#pragma unroll
            for (int j = 0; j < 8; j++) o[j] += bv[j];
        }
        float* Cp = C + (size_t)row * ldc + bn + tx * 8;
        *(float4*)Cp = *(float4*)&o[0];
        *(float4*)(Cp + 4) = *(float4*)&o[4];
    }
}

// ---------------------------------------------------------------------------
// GRU support
// ---------------------------------------------------------------------------
__global__ void init_h_kernel(float* __restrict__ h, const float* __restrict__ h0)
{
    int idx = blockIdx.x * 256 + threadIdx.x;
    h[idx] = h0[idx & (H_ - 1)];
}

__global__ void gru_gate_kernel(const float* __restrict__ xgall,
                                const float* __restrict__ hg,
                                float* __restrict__ h,
                                const int* __restrict__ slen,
                                float* __restrict__ last, int t)
{
    int idx = blockIdx.x * 256 + threadIdx.x;  // N*H
    int n = idx >> 8;
    int c = idx & 255;
    size_t xbase = ((size_t)n * T_ + t) * H3_ + c;
    size_t hbase = (size_t)n * H3_ + c;
    float xr = xgall[xbase], xz = xgall[xbase + H_], xn = xgall[xbase + 2 * H_];
    float hr = hg[hbase], hz = hg[hbase + H_], hn = hg[hbase + 2 * H_];
    float r = 1.f / (1.f + __expf(-(xr + hr)));
    float z = 1.f / (1.f + __expf(-(xz + hz)));
    float nn = tanhf(xn + r * hn);
    float hp = h[idx];
    float hnew = (1.f - z) * nn + z * hp;
    h[idx] = hnew;
    if (t == slen[n] - 1) last[idx] = hnew;
}

// ---------------------------------------------------------------------------
// Hypergraph conv support
// ---------------------------------------------------------------------------
__global__ void zero_kernel(float* __restrict__ p, int n4)
{
    int i = blockIdx.x * 256 + threadIdx.x;
    if (i < n4) ((float4*)p)[i] = make_float4(0.f, 0.f, 0.f, 0.f);
}

__global__ void count_deg_kernel(const int* __restrict__ node_idx,
                                 const int* __restrict__ edge_idx,
                                 float* __restrict__ D, float* __restrict__ B)
{
    int i = blockIdx.x * 256 + threadIdx.x;
    if (i < NNZ_) {
        atomicAdd(&D[node_idx[i]], 1.f);
        atomicAdd(&B[edge_idx[i]], 1.f);
    }
}

__global__ void make_inv_kernel(const float* __restrict__ cnt, float* __restrict__ inv, int n)
{
    int i = blockIdx.x * 256 + threadIdx.x;
    if (i < n) {
        float c = cnt[i];
        inv[i] = c > 0.f ? 1.f / c : 0.f;
    }
}

__global__ void scatter_edge_kernel(const float* __restrict__ xw,
                                    const int* __restrict__ node_idx,
                                    const int* __restrict__ edge_idx,
                                    float* __restrict__ eb)
{
    int idx = blockIdx.x * 256 + threadIdx.x;   // NNZ * 64
    int nz = idx >> 6;
    int c4 = (idx & 63) << 2;
    int n = node_idx[nz];
    int e = edge_idx[nz];
    float4 v = *(const float4*)(xw + (size_t)n * H_ + c4);
    float* dst = eb + (size_t)e * H_ + c4;
    atomicAdd(dst + 0, v.x); atomicAdd(dst + 1, v.y);
    atomicAdd(dst + 2, v.z); atomicAdd(dst + 3, v.w);
}

__global__ void scatter_node_kernel(const float* __restrict__ eb,
                                    const int* __restrict__ node_idx,
                                    const int* __restrict__ edge_idx,
                                    const float* __restrict__ Binv,
                                    float* __restrict__ agg)
{
    int idx = blockIdx.x * 256 + threadIdx.x;   // NNZ * 64
    int nz = idx >> 6;
    int c4 = (idx & 63) << 2;
    int n = node_idx[nz];
    int e = edge_idx[nz];
    float be = Binv[e];
    float4 v = *(const float4*)(eb + (size_t)e * H_ + c4);
    float* dst = agg + (size_t)n * H_ + c4;
    atomicAdd(dst + 0, v.x * be); atomicAdd(dst + 1, v.y * be);
    atomicAdd(dst + 2, v.z * be); atomicAdd(dst + 3, v.w * be);
}

__global__ void hgc_finish_kernel(const float* __restrict__ agg,
                                  const float* __restrict__ Dinv,
                                  const float* __restrict__ bias,
                                  const float* __restrict__ resid,
                                  float* __restrict__ out)
{
    int idx = blockIdx.x * 256 + threadIdx.x;   // N*H
    int n = idx >> 8;
    int c = idx & 255;
    out[idx] = agg[idx] * Dinv[n] + bias[c] + resid[idx];
}

// ---------------------------------------------------------------------------
// Final GCN: deg / dis, Y-scaling, masked GEMM
// ---------------------------------------------------------------------------
__global__ void deg_kernel(const float* __restrict__ adj,
                           const float* __restrict__ phi_p,
                           float* __restrict__ dis)
{
    int row = blockIdx.x;
    int tid = threadIdx.x;
    float thr = phi_p[0] * 65536.0f;
    const float* r = adj + (size_t)row * NN_;
    float c = 0.f;
    for (int j = tid * 4; j < NN_; j += 256 * 4) {
        float4 v = *(const float4*)(r + j);
        c += (v.x >= thr || j + 0 == row) ? 1.f : 0.f;
        c += (v.y >= thr || j + 1 == row) ? 1.f : 0.f;
        c += (v.z >= thr || j + 2 == row) ? 1.f : 0.f;
        c += (v.w >= thr || j + 3 == row) ? 1.f : 0.f;
    }
    __shared__ float sm[256];
    sm[tid] = c;
    __syncthreads();
    for (int s = 128; s > 0; s >>= 1) {
        if (tid < s) sm[tid] += sm[tid + s];
        __syncthreads();
    }
    if (tid == 0) {
        float d = sm[0];
        dis[row] = d > 0.f ? rsqrtf(d) : 0.f;
    }
}

__global__ void yscale_kernel(const float* __restrict__ x2,
                              const float* __restrict__ dis,
                              float* __restrict__ y)
{
    int idx = blockIdx.x * 256 + threadIdx.x;   // N*GCN
    int n = idx >> 8;
    y[idx] = x2[idx] * dis[n];
}

// out[i,d] = dis_i * sum_j mask(adj_ij) * Y[j,d] + bias[d]
// Same 128x128 f32x2 core as sgemm_f2; A expanded on load from the gram
// matrix via threshold compare (+forced diagonal).
__global__ __launch_bounds__(256)
void gcn_gemm_f2(const float* __restrict__ adj,
                 const float* __restrict__ Y,
                 const float* __restrict__ dis,
                 const float* __restrict__ bias,
                 const float* __restrict__ phi_p,
                 float* __restrict__ out)
{
    __shared__ __align__(16) float As[2][16][132];
    __shared__ __align__(16) float Bs[2][16][132];

    const float thr = phi_p[0] * 65536.0f;
    const int bm = blockIdx.y * 128;
    const int bn = blockIdx.x * 128;
    const int tid = threadIdx.x;
    const int tx = tid & 15;
    const int ty = tid >> 4;
    const int ar  = tid >> 2;
    const int ac4 = (tid & 3) * 4;
    const int bkr = tid >> 5;
    const int bc4 = (tid & 31) * 4;

    unsigned long long acc[8][4];
#pragma unroll
    for (int i = 0; i < 8; i++)
#pragma unroll
        for (int j = 0; j < 4; j++) acc[i][j] = 0ull;

    float4 a0v, a1v, b0v, b1v;

#define LOAD_TILE_M(k0)                                                       \
    do {                                                                      \
        int col = (k0) + ac4;                                                 \
        int row0 = bm + ar, row1 = bm + ar + 64;                              \
        float4 v0 = *(const float4*)(adj + (size_t)row0 * NN_ + col);         \
        float4 v1 = *(const float4*)(adj + (size_t)row1 * NN_ + col);         \
        a0v.x = (v0.x >= thr || row0 == col + 0) ? 1.f : 0.f;                 \
        a0v.y = (v0.y >= thr || row0 == col + 1) ? 1.f : 0.f;                 \
        a0v.z = (v0.z >= thr || row0 == col + 2) ? 1.f : 0.f;                 \
        a0v.w = (v0.w >= thr || row0 == col + 3) ? 1.f : 0.f;                 \
        a1v.x = (v1.x >= thr || row1 == col + 0) ? 1.f : 0.f;                 \
        a1v.y = (v1.y >= thr || row1 == col + 1) ? 1.f : 0.f;                 \
        a1v.z = (v1.z >= thr || row1 == col + 2) ? 1.f : 0.f;                 \
        a1v.w = (v1.w >= thr || row1 == col + 3) ? 1.f : 0.f;                 \
        const float* Bp = Y + (size_t)((k0) + bkr) * GCN_ + bn + bc4;         \
        b0v = *(const float4*)Bp;                                             \
        b1v = *(const float4*)(Bp + (size_t)8 * GCN_);                        \
    } while (0)

#define STORE_TILE_M(buf)                                                     \
    do {                                                                      \
        As[buf][ac4 + 0][ar] = a0v.x; As[buf][ac4 + 1][ar] = a0v.y;           \
        As[buf][ac4 + 2][ar] = a0v.z; As[buf][ac4 + 3][ar] = a0v.w;           \
        As[buf][ac4 + 0][ar + 64] = a1v.x; As[buf][ac4 + 1][ar + 64] = a1v.y; \
        As[buf][ac4 + 2][ar + 64] = a1v.z; As[buf][ac4 + 3][ar + 64] = a1v.w; \
        *(float4*)&Bs[buf][bkr][bc4] = b0v;                                   \
        *(float4*)&Bs[buf][bkr + 8][bc4] = b1v;                               \
    } while (0)

    LOAD_TILE_M(0);
    STORE_TILE_M(0);
    __syncthreads();

    const int nk = NN_ >> 4;
    for (int kt = 0; kt < nk; kt++) {
        const int cur = kt & 1;
        if (kt + 1 < nk) LOAD_TILE_M((kt + 1) * 16);

#pragma unroll
        for (int kk = 0; kk < 16; kk++) {
            float av[8];
            *(float4*)&av[0] = *(const float4*)&As[cur][kk][ty * 8];
            *(float4*)&av[4] = *(const float4*)&As[cur][kk][ty * 8 + 4];
            ulonglong2 bp0 = *(const ulonglong2*)&Bs[cur][kk][tx * 8];
            ulonglong2 bp1 = *(const ulonglong2*)&Bs[cur][kk][tx * 8 + 4];
#pragma unroll
            for (int i = 0; i < 8; i++) {
                unsigned long long ad = dup2(av[i]);
                fma2(acc[i][0], ad, bp0.x);
                fma2(acc[i][1], ad, bp0.y);
                fma2(acc[i][2], ad, bp1.x);
                fma2(acc[i][3], ad, bp1.y);
            }
        }
        if (kt + 1 < nk) STORE_TILE_M((kt + 1) & 1);
        __syncthreads();
    }
#undef LOAD_TILE_M
#undef STORE_TILE_M

    float bv[8];
    *(float4*)&bv[0] = *(const float4*)(bias + bn + tx * 8);
    *(float4*)&bv[4] = *(const float4*)(bias + bn + tx * 8 + 4);

#pragma unroll
    for (int i = 0; i < 8; i++) {
        int row = bm + ty * 8 + i;
        float di = dis[row];
        float o[8];
#pragma unroll
        for (int j = 0; j < 4; j++) unpack2(acc[i][j], o[2 * j], o[2 * j + 1]);
#pragma unroll
        for (int j = 0; j < 8; j++) o[j] = di * o[j] + bv[j];
        float* Cp = out + (size_t)row * GCN_ + bn + tx * 8;
        *(float4*)Cp = *(float4*)&o[0];
        *(float4*)(Cp + 4) = *(float4*)&o[4];
    }
}

// ---------------------------------------------------------------------------
// Host orchestration
// ---------------------------------------------------------------------------
static void hgc_layer(const float* in, const float* W, const float* b,
                      const int* node_idx, const int* edge_idx,
                      float* xw, float* eb, float* agg,
                      const float* Dinv, const float* Binv, float* outbuf)
{
    // xw = in @ W  (NN, 8192x256x256)
    sgemm_f2<false, false><<<dim3(H_ / 128, NN_ / 128), 256>>>(
        in, H_, W, H_, xw, H_, H_, nullptr);
    zero_kernel<<<(E_ * H_ / 4 + 255) / 256, 256>>>(eb, E_ * H_ / 4);
    scatter_edge_kernel<<<NNZ_ * 64 / 256, 256>>>(xw, node_idx, edge_idx, eb);
    zero_kernel<<<(NN_ * H_ / 4 + 255) / 256, 256>>>(agg, NN_ * H_ / 4);
    scatter_node_kernel<<<NNZ_ * 64 / 256, 256>>>(eb, node_idx, edge_idx, Binv, agg);
    hgc_finish_kernel<<<NN_ * H_ / 256, 256>>>(agg, Dinv, b, in, outbuf);
}

extern "C" void kernel_launch(void* const* d_in, const int* in_sizes, int n_in,
                              void* d_out, int out_size)
{
    (void)in_sizes; (void)n_in; (void)out_size;

    const float* x        = (const float*)d_in[0];
    const int*   hei      = (const int*)d_in[1];
    const int*   node_idx = hei;
    const int*   edge_idx = hei + NNZ_;
    const int*   slen     = (const int*)d_in[2];
    const float* h0       = (const float*)d_in[3];
    const float* W_ih     = (const float*)d_in[4];
    const float* W_hh     = (const float*)d_in[5];
    const float* b_ih     = (const float*)d_in[6];
    const float* b_hh     = (const float*)d_in[7];
    const float* w1 = (const float*)d_in[8];  const float* bb1 = (const float*)d_in[9];
    const float* w2 = (const float*)d_in[10]; const float* bb2 = (const float*)d_in[11];
    const float* w3 = (const float*)d_in[12]; const float* bb3 = (const float*)d_in[13];
    const float* phi = (const float*)d_in[14];
    const float* gw  = (const float*)d_in[15];
    const float* gb  = (const float*)d_in[16];
    float* out = (float*)d_out;

    float *adj, *xgall, *hg, *h, *fa, *fb, *xw, *eb, *agg, *x2, *y;
    float *Dcnt, *Dinv, *Bcnt, *Binv, *dis;
    cudaGetSymbolAddress((void**)&adj,   g_adj);
    cudaGetSymbolAddress((void**)&xgall, g_xgall);
    cudaGetSymbolAddress((void**)&hg,    g_hg);
    cudaGetSymbolAddress((void**)&h,     g_h);
    cudaGetSymbolAddress((void**)&fa,    g_fa);
    cudaGetSymbolAddress((void**)&fb,    g_fb);
    cudaGetSymbolAddress((void**)&xw,    g_xw);
    cudaGetSymbolAddress((void**)&eb,    g_eb);
    cudaGetSymbolAddress((void**)&agg,   g_agg);
    cudaGetSymbolAddress((void**)&x2,    g_x2);
    cudaGetSymbolAddress((void**)&y,     g_y);
    cudaGetSymbolAddress((void**)&Dcnt,  g_Dcnt);
    cudaGetSymbolAddress((void**)&Dinv,  g_Dinv);
    cudaGetSymbolAddress((void**)&Bcnt,  g_Bcnt);
    cudaGetSymbolAddress((void**)&Binv,  g_Binv);
    cudaGetSymbolAddress((void**)&dis,   g_dis);

    // ---------------- GRU ----------------
    init_h_kernel<<<NN_ * H_ / 256, 256>>>(h, h0);

    // All input gates in one large GEMM: x viewed as [N*T, IN] (contiguous).
    // xgall[n*T+t, :] = x[n,t,:] @ W_ih^T + b_ih
    sgemm_f2<true, true><<<dim3(H3_ / 128, NN_ * T_ / 128), 256>>>(
        x, IN_, W_ih, IN_, xgall, H3_, IN_, b_ih);

    for (int t = 0; t < T_; t++) {
        // hg = h @ W_hh^T + b_hh  (the only truly sequential GEMM)
        sgemm_f2<true, true><<<dim3(H3_ / 128, NN_ / 128), 256>>>(
            h, H_, W_hh, H_, hg, H3_, H_, b_hh);
        gru_gate_kernel<<<NN_ * H_ / 256, 256>>>(xgall, hg, h, slen, fa, t);
    }
    // fa now holds `last` [N,H]

    // ---------------- degrees (shared by 3 HGC layers) ----------------
    zero_kernel<<<(NN_ / 4 + 255) / 256, 256>>>(Dcnt, NN_ / 4);
    zero_kernel<<<(E_ / 4 + 255) / 256, 256>>>(Bcnt, E_ / 4);
    count_deg_kernel<<<NNZ_ / 256, 256>>>(node_idx, edge_idx, Dcnt, Bcnt);
    make_inv_kernel<<<(NN_ + 255) / 256, 256>>>(Dcnt, Dinv, NN_);
    make_inv_kernel<<<(E_ + 255) / 256, 256>>>(Bcnt, Binv, E_);

    // ---------------- 3 hypergraph conv layers with residuals ----------------
    hgc_layer(fa, w1, bb1, node_idx, edge_idx, xw, eb, agg, Dinv, Binv, fb); // o1 = fb
    hgc_layer(fb, w2, bb2, node_idx, edge_idx, xw, eb, agg, Dinv, Binv, fa); // o2 = fa
    hgc_layer(fa, w3, bb3, node_idx, edge_idx, xw, eb, agg, Dinv, Binv, fb); // o3 = fb

    // ---------------- final dense GCN ----------------
    // x2 = o3 @ gcn_w (NN)
    sgemm_f2<false, false><<<dim3(GCN_ / 128, NN_ / 128), 256>>>(
        fb, H_, gw, GCN_, x2, GCN_, H_, nullptr);
    // adj = o3 @ o3^T (NT), raw gram (compare vs phi*65536 later)
    sgemm_f2<true, false><<<dim3(NN_ / 128, NN_ / 128), 256>>>(
        fb, H_, fb, H_, adj, NN_, H_, nullptr);
    // dis_i = rsqrt(deg_i), deg includes forced diagonal
    deg_kernel<<<NN_, 256>>>(adj, phi, dis);
    // Y = dis_j * x2_j
    yscale_kernel<<<NN_ * GCN_ / 256, 256>>>(x2, dis, y);
    // out = dis_i * (mask(adj) @ Y) + gcn_b
    gcn_gemm_f2<<<dim3(GCN_ / 128, NN_ / 128), 256>>>(adj, y, dis, gb, phi, out);
}